// round 14
// baseline (speedup 1.0000x reference)
#include <cuda_runtime.h>
#include <cuda_fp16.h>
#include <cstdint>
#include <math.h>

// Problem constants
#define NT   4096          // B*T tokens
#define DM   1024          // model dim
#define FM   4096          // ffn dim
#define EM   8             // experts
#define NR   8192          // total assignments = NT * TOP_K

// ---------------------------------------------------------------------------
// Scratch (device globals; no runtime allocation allowed)
// ---------------------------------------------------------------------------
__device__ float g_usage[EM];
__device__ int   g_count[EM];
__device__ int   g_offset[EM];
__device__ int   g_cursor[EM];
__device__ int   g_tok_e[NT * 2];
__device__ float g_tok_w[NT * 2];
__device__ int   g_rowToken[NR];
__device__ float g_rowWeight[NR];
__device__ __align__(16) __half g_Hh[(size_t)NR * FM];        // h = silu(gate)*up
__device__ __align__(16) __half g_Xh[(size_t)NT * DM];        // x in fp16
__device__ __align__(16) __half g_W1h[(size_t)EM * DM * FM];  // [E][D][F] (as input)
__device__ __align__(16) __half g_W3h[(size_t)EM * DM * FM];
__device__ __align__(16) __half g_W2h[(size_t)EM * FM * DM];  // [E][F][D] (as input)

// ---------------------------------------------------------------------------
// Helpers (all non-'a' PTX: works on plain sm_103 target)
// ---------------------------------------------------------------------------
__device__ __forceinline__ uint32_t smem_u32(const void* p) {
    uint32_t a;
    asm("{ .reg .u64 t; cvta.to.shared.u64 t, %1; cvt.u32.u64 %0, t; }" : "=r"(a) : "l"(p));
    return a;
}

#define LDMX4(R, addr) \
    asm volatile("ldmatrix.sync.aligned.m8n8.x4.shared.b16 {%0,%1,%2,%3}, [%4];" \
        : "=r"((R)[0]), "=r"((R)[1]), "=r"((R)[2]), "=r"((R)[3]) : "r"(addr))

#define LDMX4T(R, addr) \
    asm volatile("ldmatrix.sync.aligned.m8n8.x4.trans.shared.b16 {%0,%1,%2,%3}, [%4];" \
        : "=r"((R)[0]), "=r"((R)[1]), "=r"((R)[2]), "=r"((R)[3]) : "r"(addr))

#define CP16(dst, src) \
    asm volatile("cp.async.cg.shared.global [%0], [%1], 16;" :: "r"(dst), "l"(src))
#define CP16Z(dst, src, sz) \
    asm volatile("cp.async.cg.shared.global [%0], [%1], 16, %2;" :: "r"(dst), "l"(src), "r"(sz))
#define CP_COMMIT() asm volatile("cp.async.commit_group;")
#define CP_WAIT(n)  asm volatile("cp.async.wait_group %0;" :: "n"(n))

// fp16 m16n8k16 mma, fp32 accum: C += A*B (in-place accumulators)
#define MMA_F16(C, A, B0, B1) \
    asm volatile("mma.sync.aligned.m16n8k16.row.col.f32.f16.f16.f32 " \
        "{%0,%1,%2,%3},{%4,%5,%6,%7},{%8,%9},{%0,%1,%2,%3};" \
        : "+f"((C)[0]), "+f"((C)[1]), "+f"((C)[2]), "+f"((C)[3]) \
        : "r"((A)[0]), "r"((A)[1]), "r"((A)[2]), "r"((A)[3]), \
          "r"(B0), "r"(B1))

// ---------------------------------------------------------------------------
// Kernel 1: zero output + counters
// ---------------------------------------------------------------------------
__global__ void zero_kernel(float* __restrict__ out) {
    int idx = blockIdx.x * blockDim.x + threadIdx.x;
    int stride = gridDim.x * blockDim.x;
    for (int i = idx; i < NT * DM; i += stride) out[i] = 0.0f;
    if (idx < EM) { g_count[idx] = 0; g_usage[idx] = 0.0f; }
}

// ---------------------------------------------------------------------------
// Kernel 2: router (fp32 selection) + fused x -> fp16 conversion
// ---------------------------------------------------------------------------
__global__ __launch_bounds__(256) void router_kernel(const float* __restrict__ x,
                                                     const float* __restrict__ Wr) {
    int t = blockIdx.x;
    int tid = threadIdx.x;
    float acc[EM];
#pragma unroll
    for (int e = 0; e < EM; e++) acc[e] = 0.0f;
    const float4 xv = *reinterpret_cast<const float4*>(x + (size_t)t * DM + tid * 4);

    // fused: write fp16 copy of x
    __half2* xh = reinterpret_cast<__half2*>(g_Xh + (size_t)t * DM + tid * 4);
    xh[0] = __floats2half2_rn(xv.x, xv.y);
    xh[1] = __floats2half2_rn(xv.z, xv.w);

    const float xs[4] = {xv.x, xv.y, xv.z, xv.w};
#pragma unroll
    for (int i = 0; i < 4; i++) {
        const float4* wr = reinterpret_cast<const float4*>(Wr + (size_t)(tid * 4 + i) * EM);
        float4 a = wr[0], b = wr[1];
        float xd = xs[i];
        acc[0] += xd * a.x; acc[1] += xd * a.y; acc[2] += xd * a.z; acc[3] += xd * a.w;
        acc[4] += xd * b.x; acc[5] += xd * b.y; acc[6] += xd * b.z; acc[7] += xd * b.w;
    }
#pragma unroll
    for (int e = 0; e < EM; e++)
#pragma unroll
        for (int off = 16; off; off >>= 1)
            acc[e] += __shfl_down_sync(0xffffffffu, acc[e], off);
    __shared__ float ws[8][EM];
    int lane = tid & 31, warp = tid >> 5;
    if (lane == 0) {
#pragma unroll
        for (int e = 0; e < EM; e++) ws[warp][e] = acc[e];
    }
    __syncthreads();
    if (tid == 0) {
        float lg[EM];
#pragma unroll
        for (int e = 0; e < EM; e++) {
            float s = 0.0f;
#pragma unroll
            for (int w = 0; w < 8; w++) s += ws[w][e];
            lg[e] = s;
        }
        float m = lg[0];
#pragma unroll
        for (int e = 1; e < EM; e++) m = fmaxf(m, lg[e]);
        float p[EM], s = 0.0f;
#pragma unroll
        for (int e = 0; e < EM; e++) { p[e] = expf(lg[e] - m); s += p[e]; }
        float inv = 1.0f / s;
#pragma unroll
        for (int e = 0; e < EM; e++) atomicAdd(&g_usage[e], p[e] * inv);
        int i0 = 0;
#pragma unroll
        for (int e = 1; e < EM; e++) if (lg[e] > lg[i0]) i0 = e;
        int i1 = -1;
#pragma unroll
        for (int e = 0; e < EM; e++)
            if (e != i0 && (i1 < 0 || lg[e] > lg[i1])) i1 = e;
        float e1 = expf(lg[i1] - lg[i0]);
        float sw = 1.0f + e1;
        g_tok_e[2 * t + 0] = i0;
        g_tok_e[2 * t + 1] = i1;
        g_tok_w[2 * t + 0] = 1.0f / sw;
        g_tok_w[2 * t + 1] = e1 / sw;
        atomicAdd(&g_count[i0], 1);
        atomicAdd(&g_count[i1], 1);
    }
}

// ---------------------------------------------------------------------------
// Kernel 3: prefix + loss + scatter (single block)
// ---------------------------------------------------------------------------
__global__ __launch_bounds__(256) void prefix_scatter_kernel(float* __restrict__ out,
                                                             int out_size) {
    if (threadIdx.x == 0) {
        int off = 0;
#pragma unroll
        for (int e = 0; e < EM; e++) {
            g_offset[e] = off;
            g_cursor[e] = off;
            off += g_count[e];
        }
        float loss = 0.0f;
#pragma unroll
        for (int e = 0; e < EM; e++) {
            float u = g_usage[e] * (1.0f / (float)NT);
            loss += u * u;
        }
        loss *= (float)EM;
        if (out_size > NT * DM) out[NT * DM] = loss;
    }
    __syncthreads();
    for (int t = threadIdx.x; t < NT; t += 256) {
#pragma unroll
        for (int k = 0; k < 2; k++) {
            int e = g_tok_e[2 * t + k];
            int pos = atomicAdd(&g_cursor[e], 1);
            g_rowToken[pos] = t;
            g_rowWeight[pos] = g_tok_w[2 * t + k];
        }
    }
}

// ---------------------------------------------------------------------------
// Kernel C: streaming fp32 -> fp16 convert of W1, W3, W2 (no transpose;
// layout preserved). One thread = 8 elements (2x float4 in, 1x uint4 out).
// ---------------------------------------------------------------------------
__global__ __launch_bounds__(256) void cvt_weights(const float* __restrict__ W1,
                                                   const float* __restrict__ W3,
                                                   const float* __restrict__ W2) {
    const size_t N8 = (size_t)EM * DM * FM / 8;
    size_t i = (size_t)blockIdx.x * blockDim.x + threadIdx.x;
    const float* src;
    __half* dst;
    if (i < N8) { src = W1; dst = g_W1h; }
    else if (i < 2 * N8) { src = W3; dst = g_W3h; i -= N8; }
    else { src = W2; dst = g_W2h; i -= 2 * N8; }
    float4 a = reinterpret_cast<const float4*>(src)[2 * i];
    float4 b = reinterpret_cast<const float4*>(src)[2 * i + 1];
    __half2 h[4];
    h[0] = __floats2half2_rn(a.x, a.y);
    h[1] = __floats2half2_rn(a.z, a.w);
    h[2] = __floats2half2_rn(b.x, b.y);
    h[3] = __floats2half2_rn(b.z, b.w);
    reinterpret_cast<uint4*>(dst)[i] = *reinterpret_cast<uint4*>(h);
}

// ---------------------------------------------------------------------------
// Kernel 5: ffn1, fp16 mma + ldmatrix. BM=128 x BN=64 (gate AND up), BK=64.
// A tile [m][k] (non-trans ldmatrix); B tiles [k][n] K-major as in gmem,
// read with ldmatrix.trans. smem stage: A 16KB | B1 8KB | B3 8KB = 32KB, x2.
// 8 warps 4(m) x 2(n); warp tile 32x32 dual.
// ---------------------------------------------------------------------------
#define F1_STAGE 32768
#define F1_SMEM  (2 * F1_STAGE)

__global__ __launch_bounds__(256) void ffn1_mma() {
    int e = blockIdx.z;
    int n_e = g_count[e];
    int m0 = blockIdx.x * 128;
    if (m0 >= n_e) return;
    int f0 = blockIdx.y * 64;
    int rbase = g_offset[e];
    extern __shared__ char smem[];
    uint32_t sbase = smem_u32(smem);
    int tid = threadIdx.x, wid = tid >> 5, lane = tid & 31;
    int wm = (wid >> 1) * 32, wn = (wid & 1) * 32;

    // ldmatrix per-thread geometry
    int r8 = lane & 7, quad = lane >> 3;
    int aq = quad >> 1;              // A chunk parity add
    int am8 = (quad & 1) * 8;        // A row +8
    uint32_t arowoff[2];
#pragma unroll
    for (int mi = 0; mi < 2; mi++)
        arowoff[mi] = (uint32_t)((wm + mi * 16 + am8 + r8) * 128);
    // B (trans): k-row offset = (quad&1)*8 + r8; n-chunk = wn/8 + np*2 + (quad>>1)
    uint32_t browoff[2];
#pragma unroll
    for (int np = 0; np < 2; np++) {
        int chunk = (wn >> 3) + np * 2 + (quad >> 1);
        browoff[np] = (uint32_t)((((quad & 1) * 8 + r8) * 128) + (((chunk ^ r8)) << 4));
    }

    // A loader: chunk = (row, c16); row = tid>>3 (+32*i), c16 = tid&7
    int lrow = tid >> 3;
    int c16 = tid & 7;
    const __half* asrc[4];
    uint32_t asz[4], adst[4];
#pragma unroll
    for (int i = 0; i < 4; i++) {
        int row = lrow + 32 * i;
        int grow = m0 + row;
        int tok = (grow < n_e) ? g_rowToken[rbase + grow] : 0;
        asrc[i] = g_Xh + (size_t)tok * DM + c16 * 8;
        asz[i] = (grow < n_e) ? 16u : 0u;
        adst[i] = (uint32_t)(row * 128 + ((c16 ^ (row & 7)) * 16));
    }
    // B loader (K-major): 4 threads per k-row, 2 chunks each per matrix
    int lrowB = tid >> 2, bq = tid & 3;
    const __half* b1src = g_W1h + (size_t)e * DM * FM + (size_t)lrowB * FM + f0 + bq * 16;
    const __half* b3src = g_W3h + (size_t)e * DM * FM + (size_t)lrowB * FM + f0 + bq * 16;
    uint32_t bdst0 = (uint32_t)(lrowB * 128 + (((bq * 2) ^ (lrowB & 7)) << 4));
    uint32_t bdst1 = (uint32_t)(lrowB * 128 + (((bq * 2 + 1) ^ (lrowB & 7)) << 4));

    float ag[2][4][4], au[2][4][4];
#pragma unroll
    for (int mi = 0; mi < 2; mi++)
#pragma unroll
        for (int ni = 0; ni < 4; ni++)
#pragma unroll
            for (int j = 0; j < 4; j++) { ag[mi][ni][j] = 0.0f; au[mi][ni][j] = 0.0f; }

#define F1_FILL(s, c) do {                                               \
        uint32_t ab_ = sbase + (s) * F1_STAGE;                           \
        uint32_t b1_ = ab_ + 16384, b3_ = ab_ + 24576;                   \
        _Pragma("unroll")                                                \
        for (int i_ = 0; i_ < 4; i_++)                                   \
            CP16Z(ab_ + adst[i_], asrc[i_] + (c) * 64, asz[i_]);         \
        const __half* b1p_ = b1src + (size_t)(c) * 64 * FM;              \
        const __half* b3p_ = b3src + (size_t)(c) * 64 * FM;              \
        CP16(b1_ + bdst0, b1p_);                                         \
        CP16(b1_ + bdst1, b1p_ + 8);                                     \
        CP16(b3_ + bdst0, b3p_);                                         \
        CP16(b3_ + bdst1, b3p_ + 8);                                     \
    } while (0)

    F1_FILL(0, 0);
    CP_COMMIT();
    const int NKC = DM / 64;           // 64 halves per chunk
    for (int c = 0; c < NKC; c++) {
        int p = c & 1;
        if (c + 1 < NKC) {
            F1_FILL(p ^ 1, c + 1);
            CP_COMMIT();
            CP_WAIT(1);
        } else {
            CP_WAIT(0);
        }
        __syncthreads();
        uint32_t ab = sbase + p * F1_STAGE;
        uint32_t b1b = ab + 16384, b3b = ab + 24576;
#pragma unroll
        for (int s = 0; s < 4; s++) {          // 4 k16-steps per 64-half chunk
            uint32_t aco = (uint32_t)((((2 * s + aq) ^ r8) << 4));
            uint32_t bko = (uint32_t)(s * 2048);   // 16 k-rows * 128B
            uint32_t am[2][4], qb1[2][4], qb3[2][4];
            LDMX4(am[0], ab + arowoff[0] + aco);
            LDMX4(am[1], ab + arowoff[1] + aco);
            LDMX4T(qb1[0], b1b + browoff[0] + bko);
            LDMX4T(qb1[1], b1b + browoff[1] + bko);
            LDMX4T(qb3[0], b3b + browoff[0] + bko);
            LDMX4T(qb3[1], b3b + browoff[1] + bko);
#pragma unroll
            for (int mi = 0; mi < 2; mi++)
#pragma unroll
                for (int ni = 0; ni < 4; ni++) {
                    MMA_F16(ag[mi][ni], am[mi], qb1[ni >> 1][(ni & 1) * 2], qb1[ni >> 1][(ni & 1) * 2 + 1]);
                    MMA_F16(au[mi][ni], am[mi], qb3[ni >> 1][(ni & 1) * 2], qb3[ni >> 1][(ni & 1) * 2 + 1]);
                }
        }
        __syncthreads();
    }

    // epilogue: h = silu(gate)*up -> g_Hh (fp16)
    int g = lane >> 2, tig = lane & 3;
#pragma unroll
    for (int mi = 0; mi < 2; mi++)
#pragma unroll
        for (int half = 0; half < 2; half++) {
            int row = m0 + wm + mi * 16 + g + half * 8;
            if (row < n_e) {
                __half* hr = g_Hh + (size_t)(rbase + row) * FM + f0 + wn;
#pragma unroll
                for (int ni = 0; ni < 4; ni++) {
                    float gv0 = ag[mi][ni][half * 2 + 0];
                    float gv1 = ag[mi][ni][half * 2 + 1];
                    float uv0 = au[mi][ni][half * 2 + 0];
                    float uv1 = au[mi][ni][half * 2 + 1];
                    float h0 = gv0 * uv0 / (1.0f + __expf(-gv0));
                    float h1 = gv1 * uv1 / (1.0f + __expf(-gv1));
                    *reinterpret_cast<__half2*>(hr + ni * 8 + 2 * tig) =
                        __floats2half2_rn(h0, h1);
                }
            }
        }
#undef F1_FILL
}

// ---------------------------------------------------------------------------
// Kernel 6: ffn2, fp16 mma + ldmatrix. BM=128 x BN=64, BK=64, K=FM.
// A = H [m][k]; B = W2 [k=f][n=d] K-major as in gmem, ldmatrix.trans.
// smem stage: A 16KB | B 8KB = 24KB, double buffered.
// ---------------------------------------------------------------------------
#define F2_STAGE 24576
#define F2_SMEM  (2 * F2_STAGE)

__global__ __launch_bounds__(256) void ffn2_mma(float* __restrict__ out) {
    int e = blockIdx.z;
    int n_e = g_count[e];
    int m0 = blockIdx.x * 128;
    if (m0 >= n_e) return;
    int n0 = blockIdx.y * 64;
    int rbase = g_offset[e];
    extern __shared__ char smem[];
    uint32_t sbase = smem_u32(smem);
    int tid = threadIdx.x, wid = tid >> 5, lane = tid & 31;
    int wm = (wid >> 1) * 32, wn = (wid & 1) * 32;

    int r8 = lane & 7, quad = lane >> 3;
    int aq = quad >> 1;
    int am8 = (quad & 1) * 8;
    uint32_t arowoff[2];
#pragma unroll
    for (int mi = 0; mi < 2; mi++)
        arowoff[mi] = (uint32_t)((wm + mi * 16 + am8 + r8) * 128);
    uint32_t browoff[2];
#pragma unroll
    for (int np = 0; np < 2; np++) {
        int chunk = (wn >> 3) + np * 2 + (quad >> 1);
        browoff[np] = (uint32_t)((((quad & 1) * 8 + r8) * 128) + (((chunk ^ r8)) << 4));
    }

    int lrow = tid >> 3;
    int c16 = tid & 7;
    const __half* asrc[4];
    uint32_t asz[4], adst[4];
#pragma unroll
    for (int i = 0; i < 4; i++) {
        int row = lrow + 32 * i;
        int grow = m0 + row;
        asrc[i] = g_Hh + (size_t)(rbase + ((grow < n_e) ? grow : 0)) * FM + c16 * 8;
        asz[i] = (grow < n_e) ? 16u : 0u;
        adst[i] = (uint32_t)(row * 128 + ((c16 ^ (row & 7)) * 16));
    }
    int lrowB = tid >> 2, bq = tid & 3;
    const __half* bsrc = g_W2h + (size_t)e * FM * DM + (size_t)lrowB * DM + n0 + bq * 16;
    uint32_t bdst0 = (uint32_t)(lrowB * 128 + (((bq * 2) ^ (lrowB & 7)) << 4));
    uint32_t bdst1 = (uint32_t)(lrowB * 128 + (((bq * 2 + 1) ^ (lrowB & 7)) << 4));

    float acc[2][4][4];
#pragma unroll
    for (int mi = 0; mi < 2; mi++)
#pragma unroll
        for (int ni = 0; ni < 4; ni++)
#pragma unroll
            for (int j = 0; j < 4; j++) acc[mi][ni][j] = 0.0f;

#define F2_FILL(s, c) do {                                               \
        uint32_t ab_ = sbase + (s) * F2_STAGE;                           \
        uint32_t bb_ = ab_ + 16384;                                      \
        _Pragma("unroll")                                                \
        for (int i_ = 0; i_ < 4; i_++)                                   \
            CP16Z(ab_ + adst[i_], asrc[i_] + (c) * 64, asz[i_]);         \
        const __half* bp_ = bsrc + (size_t)(c) * 64 * DM;                \
        CP16(bb_ + bdst0, bp_);                                          \
        CP16(bb_ + bdst1, bp_ + 8);                                      \
    } while (0)

    F2_FILL(0, 0);
    CP_COMMIT();
    const int NKC = FM / 64;
    for (int c = 0; c < NKC; c++) {
        int p = c & 1;
        if (c + 1 < NKC) {
            F2_FILL(p ^ 1, c + 1);
            CP_COMMIT();
            CP_WAIT(1);
        } else {
            CP_WAIT(0);
        }
        __syncthreads();
        uint32_t ab = sbase + p * F2_STAGE;
        uint32_t bb = ab + 16384;
#pragma unroll
        for (int s = 0; s < 4; s++) {
            uint32_t aco = (uint32_t)((((2 * s + aq) ^ r8) << 4));
            uint32_t bko = (uint32_t)(s * 2048);
            uint32_t am[2][4], qb[2][4];
            LDMX4(am[0], ab + arowoff[0] + aco);
            LDMX4(am[1], ab + arowoff[1] + aco);
            LDMX4T(qb[0], bb + browoff[0] + bko);
            LDMX4T(qb[1], bb + browoff[1] + bko);
#pragma unroll
            for (int mi = 0; mi < 2; mi++)
#pragma unroll
                for (int ni = 0; ni < 4; ni++)
                    MMA_F16(acc[mi][ni], am[mi], qb[ni >> 1][(ni & 1) * 2], qb[ni >> 1][(ni & 1) * 2 + 1]);
        }
        __syncthreads();
    }

    // epilogue: weighted atomicAdd into out[token]
    int g = lane >> 2, tig = lane & 3;
#pragma unroll
    for (int mi = 0; mi < 2; mi++)
#pragma unroll
        for (int half = 0; half < 2; half++) {
            int row = m0 + wm + mi * 16 + g + half * 8;
            if (row < n_e) {
                int gi = rbase + row;
                float wgt = g_rowWeight[gi];
                int tok = g_rowToken[gi];
                float* orow = out + (size_t)tok * DM + n0 + wn;
#pragma unroll
                for (int ni = 0; ni < 4; ni++) {
                    atomicAdd(orow + ni * 8 + 2 * tig,     wgt * acc[mi][ni][half * 2 + 0]);
                    atomicAdd(orow + ni * 8 + 2 * tig + 1, wgt * acc[mi][ni][half * 2 + 1]);
                }
            }
        }
#undef F2_FILL
}

// ---------------------------------------------------------------------------
// Launch
// ---------------------------------------------------------------------------
extern "C" void kernel_launch(void* const* d_in, const int* in_sizes, int n_in,
                              void* d_out, int out_size) {
    const float* x  = (const float*)d_in[0];   // [B,T,D]
    const float* Wr = (const float*)d_in[1];   // [D,E]
    const float* W1 = (const float*)d_in[2];   // [E,D,F]
    const float* W3 = (const float*)d_in[3];   // [E,D,F]
    const float* W2 = (const float*)d_in[4];   // [E,F,D]
    float* out = (float*)d_out;

    cudaFuncSetAttribute(ffn1_mma, cudaFuncAttributeMaxDynamicSharedMemorySize, F1_SMEM);
    cudaFuncSetAttribute(ffn2_mma, cudaFuncAttributeMaxDynamicSharedMemorySize, F2_SMEM);

    zero_kernel<<<4096, 256>>>(out);
    router_kernel<<<NT, 256>>>(x, Wr);          // also writes g_Xh
    prefix_scatter_kernel<<<1, 256>>>(out, out_size);

    // 3 * EM*DM*FM / 8 elements-per-thread / 256 threads
    cvt_weights<<<(unsigned)(3u * EM * DM * (FM / 8) / 256), 256>>>(W1, W3, W2);

    ffn1_mma<<<dim3(32, FM / 64, EM), 256, F1_SMEM>>>();
    ffn2_mma<<<dim3(32, DM / 64, EM), 256, F2_SMEM>>>(out);
}

// round 16
// speedup vs baseline: 1.1997x; 1.1997x over previous
#include <cuda_runtime.h>
#include <cuda_fp16.h>
#include <cstdint>
#include <math.h>

// Problem constants
#define NT   4096          // B*T tokens
#define DM   1024          // model dim
#define FM   4096          // ffn dim
#define EM   8             // experts
#define NR   8192          // total assignments = NT * TOP_K

// ---------------------------------------------------------------------------
// Scratch (device globals; no runtime allocation allowed)
// ---------------------------------------------------------------------------
__device__ float g_usage[EM];
__device__ int   g_count[EM];
__device__ int   g_offset[EM];
__device__ int   g_cursor[EM];
__device__ int   g_tok_e[NT * 2];
__device__ float g_tok_w[NT * 2];
__device__ int   g_rowToken[NR];
__device__ float g_rowWeight[NR];
__device__ __align__(16) __half g_Hh[(size_t)NR * FM];        // h = silu(gate)*up
__device__ __align__(16) __half g_Xh[(size_t)NT * DM];        // x in fp16
__device__ __align__(16) __half g_W1h[(size_t)EM * FM * DM];  // [E][F][D] transposed
__device__ __align__(16) __half g_W3h[(size_t)EM * FM * DM];
__device__ __align__(16) __half g_W2h[(size_t)EM * DM * FM];  // [E][D][F] transposed

// ---------------------------------------------------------------------------
// Helpers (all non-'a' PTX: works on plain sm_103 target)
// ---------------------------------------------------------------------------
__device__ __forceinline__ uint32_t smem_u32(const void* p) {
    uint32_t a;
    asm("{ .reg .u64 t; cvta.to.shared.u64 t, %1; cvt.u32.u64 %0, t; }" : "=r"(a) : "l"(p));
    return a;
}

#define LDMX4(R, addr) \
    asm volatile("ldmatrix.sync.aligned.m8n8.x4.shared.b16 {%0,%1,%2,%3}, [%4];" \
        : "=r"((R)[0]), "=r"((R)[1]), "=r"((R)[2]), "=r"((R)[3]) : "r"(addr))

#define CP16(dst, src) \
    asm volatile("cp.async.cg.shared.global [%0], [%1], 16;" :: "r"(dst), "l"(src))
#define CP16Z(dst, src, sz) \
    asm volatile("cp.async.cg.shared.global [%0], [%1], 16, %2;" :: "r"(dst), "l"(src), "r"(sz))
#define CP_COMMIT() asm volatile("cp.async.commit_group;")
#define CP_WAIT(n)  asm volatile("cp.async.wait_group %0;" :: "n"(n))

// fp16 m16n8k16 mma, fp32 accum: C += A*B (in-place accumulators)
#define MMA_F16(C, A, B0, B1) \
    asm volatile("mma.sync.aligned.m16n8k16.row.col.f32.f16.f16.f32 " \
        "{%0,%1,%2,%3},{%4,%5,%6,%7},{%8,%9},{%0,%1,%2,%3};" \
        : "+f"((C)[0]), "+f"((C)[1]), "+f"((C)[2]), "+f"((C)[3]) \
        : "r"((A)[0]), "r"((A)[1]), "r"((A)[2]), "r"((A)[3]), \
          "r"(B0), "r"(B1))

// ---------------------------------------------------------------------------
// Kernel 1: zero output + counters
// ---------------------------------------------------------------------------
__global__ void zero_kernel(float* __restrict__ out) {
    int idx = blockIdx.x * blockDim.x + threadIdx.x;
    int stride = gridDim.x * blockDim.x;
    for (int i = idx; i < NT * DM; i += stride) out[i] = 0.0f;
    if (idx < EM) { g_count[idx] = 0; g_usage[idx] = 0.0f; }
}

// ---------------------------------------------------------------------------
// Kernel 2: router (fp32 selection) + fused x -> fp16 conversion
// ---------------------------------------------------------------------------
__global__ __launch_bounds__(256) void router_kernel(const float* __restrict__ x,
                                                     const float* __restrict__ Wr) {
    int t = blockIdx.x;
    int tid = threadIdx.x;
    float acc[EM];
#pragma unroll
    for (int e = 0; e < EM; e++) acc[e] = 0.0f;
    const float4 xv = *reinterpret_cast<const float4*>(x + (size_t)t * DM + tid * 4);

    // fused: write fp16 copy of x
    __half2* xh = reinterpret_cast<__half2*>(g_Xh + (size_t)t * DM + tid * 4);
    xh[0] = __floats2half2_rn(xv.x, xv.y);
    xh[1] = __floats2half2_rn(xv.z, xv.w);

    const float xs[4] = {xv.x, xv.y, xv.z, xv.w};
#pragma unroll
    for (int i = 0; i < 4; i++) {
        const float4* wr = reinterpret_cast<const float4*>(Wr + (size_t)(tid * 4 + i) * EM);
        float4 a = wr[0], b = wr[1];
        float xd = xs[i];
        acc[0] += xd * a.x; acc[1] += xd * a.y; acc[2] += xd * a.z; acc[3] += xd * a.w;
        acc[4] += xd * b.x; acc[5] += xd * b.y; acc[6] += xd * b.z; acc[7] += xd * b.w;
    }
#pragma unroll
    for (int e = 0; e < EM; e++)
#pragma unroll
        for (int off = 16; off; off >>= 1)
            acc[e] += __shfl_down_sync(0xffffffffu, acc[e], off);
    __shared__ float ws[8][EM];
    int lane = tid & 31, warp = tid >> 5;
    if (lane == 0) {
#pragma unroll
        for (int e = 0; e < EM; e++) ws[warp][e] = acc[e];
    }
    __syncthreads();
    if (tid == 0) {
        float lg[EM];
#pragma unroll
        for (int e = 0; e < EM; e++) {
            float s = 0.0f;
#pragma unroll
            for (int w = 0; w < 8; w++) s += ws[w][e];
            lg[e] = s;
        }
        float m = lg[0];
#pragma unroll
        for (int e = 1; e < EM; e++) m = fmaxf(m, lg[e]);
        float p[EM], s = 0.0f;
#pragma unroll
        for (int e = 0; e < EM; e++) { p[e] = expf(lg[e] - m); s += p[e]; }
        float inv = 1.0f / s;
#pragma unroll
        for (int e = 0; e < EM; e++) atomicAdd(&g_usage[e], p[e] * inv);
        int i0 = 0;
#pragma unroll
        for (int e = 1; e < EM; e++) if (lg[e] > lg[i0]) i0 = e;
        int i1 = -1;
#pragma unroll
        for (int e = 0; e < EM; e++)
            if (e != i0 && (i1 < 0 || lg[e] > lg[i1])) i1 = e;
        float e1 = expf(lg[i1] - lg[i0]);
        float sw = 1.0f + e1;
        g_tok_e[2 * t + 0] = i0;
        g_tok_e[2 * t + 1] = i1;
        g_tok_w[2 * t + 0] = 1.0f / sw;
        g_tok_w[2 * t + 1] = e1 / sw;
        atomicAdd(&g_count[i0], 1);
        atomicAdd(&g_count[i1], 1);
    }
}

// ---------------------------------------------------------------------------
// Kernel 3: prefix + loss + scatter (single block)
// ---------------------------------------------------------------------------
__global__ __launch_bounds__(256) void prefix_scatter_kernel(float* __restrict__ out,
                                                             int out_size) {
    if (threadIdx.x == 0) {
        int off = 0;
#pragma unroll
        for (int e = 0; e < EM; e++) {
            g_offset[e] = off;
            g_cursor[e] = off;
            off += g_count[e];
        }
        float loss = 0.0f;
#pragma unroll
        for (int e = 0; e < EM; e++) {
            float u = g_usage[e] * (1.0f / (float)NT);
            loss += u * u;
        }
        loss *= (float)EM;
        if (out_size > NT * DM) out[NT * DM] = loss;
    }
    __syncthreads();
    for (int t = threadIdx.x; t < NT; t += 256) {
#pragma unroll
        for (int k = 0; k < 2; k++) {
            int e = g_tok_e[2 * t + k];
            int pos = atomicAdd(&g_cursor[e], 1);
            g_rowToken[pos] = t;
            g_rowWeight[pos] = g_tok_w[2 * t + k];
        }
    }
}

// ---------------------------------------------------------------------------
// Kernel T: single-launch transpose+convert for W1, W3, W2.
// Tile = 32 (c) x 64 (r); loads 128B-coalesced fp32, stores __half2 (4B)
// fully coalesced. 1-D grid, no empty blocks.
//   W1/W3: [D][F] -> [f][d]  (R=DM rows of dst, C=FM)
//   W2:    [F][D] -> [d][f]  (R=FM, C=DM)
// ---------------------------------------------------------------------------
#define T13_TILES 2048          // (FM/32) * (DM/64) = 128 * 16
#define TW2_TILES 2048          // (DM/32) * (FM/64) = 32 * 64
#define T_TOTAL   (T13_TILES * 2 * EM + TW2_TILES * EM)   // 49152

__global__ __launch_bounds__(256) void transpose_all(const float* __restrict__ W1,
                                                     const float* __restrict__ W3,
                                                     const float* __restrict__ W2) {
    __shared__ float tile[32][65];
    int b = blockIdx.x;
    const float* src;
    __half* dst;
    int R, C, c0, r0;
    if (b < T13_TILES * 2 * EM) {
        int plane = b >> 11;          // /T13_TILES
        int ti = b & (T13_TILES - 1);
        R = DM; C = FM;
        size_t off = (size_t)((plane < EM) ? plane : plane - EM) * DM * FM;
        src = ((plane < EM) ? W1 : W3) + off;
        dst = ((plane < EM) ? g_W1h : g_W3h) + off;
        c0 = (ti & 127) * 32;         // 128 c-tiles over F
        r0 = (ti >> 7) * 64;          // 16 r-tiles over D
    } else {
        b -= T13_TILES * 2 * EM;
        int plane = b >> 11;
        int ti = b & (TW2_TILES - 1);
        R = FM; C = DM;
        size_t off = (size_t)plane * DM * FM;
        src = W2 + off;
        dst = g_W2h + off;
        c0 = (ti & 31) * 32;          // 32 c-tiles over D
        r0 = (ti >> 5) * 64;          // 64 r-tiles over F
    }
    int tx = threadIdx.x & 31, ty = threadIdx.x >> 5;
    // load: 64 rows x 32 cols, coalesced along c
#pragma unroll
    for (int i = 0; i < 8; i++) {
        int r = ty + i * 8;
        tile[tx][r] = src[(size_t)(r0 + r) * C + c0 + tx];
    }
    __syncthreads();
    // store: for each c, 64 r-values as 32 half2 -> 128B per warp
#pragma unroll
    for (int j = 0; j < 4; j++) {
        int c = ty + j * 8;
        __half2 v = __floats2half2_rn(tile[c][2 * tx], tile[c][2 * tx + 1]);
        *reinterpret_cast<__half2*>(&dst[(size_t)(c0 + c) * R + r0 + 2 * tx]) = v;
    }
}

// ---------------------------------------------------------------------------
// Kernel 5: ffn1, fp16 mma + ldmatrix. BM=128 x BN=64 (gate AND up), BK=64 halves.
// smem stage: A 16KB | B1 8KB | B3 8KB = 32KB, double buffered.
// 8 warps 4(m) x 2(n); warp tile 32x32 dual.  (R9 proven config)
// ---------------------------------------------------------------------------
#define F1_STAGE 32768
#define F1_SMEM  (2 * F1_STAGE)

__global__ __launch_bounds__(256) void ffn1_mma() {
    int e = blockIdx.z;
    int n_e = g_count[e];
    int m0 = blockIdx.x * 128;
    if (m0 >= n_e) return;
    int f0 = blockIdx.y * 64;
    int rbase = g_offset[e];
    extern __shared__ char smem[];
    uint32_t sbase = smem_u32(smem);
    int tid = threadIdx.x, wid = tid >> 5, lane = tid & 31;
    int wm = (wid >> 1) * 32, wn = (wid & 1) * 32;

    // ldmatrix per-thread geometry
    int r8 = lane & 7, quad = lane >> 3;
    int aq = quad >> 1;              // A chunk parity add
    int am8 = (quad & 1) * 8;        // A row +8
    int bq = quad & 1;               // B chunk parity add
    int bm8 = (quad >> 1) * 8;       // B row +8
    uint32_t arowoff[2], browoff[2];
#pragma unroll
    for (int mi = 0; mi < 2; mi++)
        arowoff[mi] = (uint32_t)((wm + mi * 16 + am8 + r8) * 128);
#pragma unroll
    for (int np = 0; np < 2; np++)
        browoff[np] = (uint32_t)((wn + np * 16 + bm8 + r8) * 128);

    // loaders: chunk = (row, c16); row = tid>>3 (+32*i), c16 = tid&7 (16B = 8 halves)
    int lrow = tid >> 3;
    int c16 = tid & 7;
    const __half* asrc[4];
    uint32_t asz[4], adst[4];
#pragma unroll
    for (int i = 0; i < 4; i++) {
        int row = lrow + 32 * i;
        int grow = m0 + row;
        int tok = (grow < n_e) ? g_rowToken[rbase + grow] : 0;
        asrc[i] = g_Xh + (size_t)tok * DM + c16 * 8;
        asz[i] = (grow < n_e) ? 16u : 0u;
        adst[i] = (uint32_t)(row * 128 + ((c16 ^ (row & 7)) * 16));
    }
    const __half* b1src[2];
    const __half* b3src[2];
    uint32_t bdst[2];
#pragma unroll
    for (int i = 0; i < 2; i++) {
        int row = lrow + 32 * i;
        b1src[i] = g_W1h + ((size_t)e * FM + f0 + row) * DM + c16 * 8;
        b3src[i] = g_W3h + ((size_t)e * FM + f0 + row) * DM + c16 * 8;
        bdst[i] = (uint32_t)(row * 128 + ((c16 ^ (row & 7)) * 16));
    }

    float ag[2][4][4], au[2][4][4];
#pragma unroll
    for (int mi = 0; mi < 2; mi++)
#pragma unroll
        for (int ni = 0; ni < 4; ni++)
#pragma unroll
            for (int j = 0; j < 4; j++) { ag[mi][ni][j] = 0.0f; au[mi][ni][j] = 0.0f; }

#define F1_FILL(s, k0) do {                                              \
        uint32_t ab_ = sbase + (s) * F1_STAGE;                           \
        uint32_t b1_ = ab_ + 16384, b3_ = ab_ + 24576;                   \
        _Pragma("unroll")                                                \
        for (int i_ = 0; i_ < 4; i_++) CP16Z(ab_ + adst[i_], asrc[i_] + (k0), asz[i_]); \
        _Pragma("unroll")                                                \
        for (int i_ = 0; i_ < 2; i_++) {                                 \
            CP16(b1_ + bdst[i_], b1src[i_] + (k0));                      \
            CP16(b3_ + bdst[i_], b3src[i_] + (k0));                      \
        } } while (0)

    F1_FILL(0, 0);
    CP_COMMIT();
    const int NKC = DM / 64;           // 64 halves per chunk
    for (int c = 0; c < NKC; c++) {
        int p = c & 1;
        if (c + 1 < NKC) {
            F1_FILL(p ^ 1, (c + 1) * 64);
            CP_COMMIT();
            CP_WAIT(1);
        } else {
            CP_WAIT(0);
        }
        __syncthreads();
        uint32_t ab = sbase + p * F1_STAGE;
        uint32_t b1b = ab + 16384, b3b = ab + 24576;
#pragma unroll
        for (int s = 0; s < 4; s++) {          // 4 k16-steps per 64-half chunk
            uint32_t aco = (uint32_t)((((2 * s + aq) ^ r8) << 4));
            uint32_t bco = (uint32_t)((((2 * s + bq) ^ r8) << 4));
            uint32_t am[2][4], qb1[2][4], qb3[2][4];
            LDMX4(am[0], ab + arowoff[0] + aco);
            LDMX4(am[1], ab + arowoff[1] + aco);
            LDMX4(qb1[0], b1b + browoff[0] + bco);
            LDMX4(qb1[1], b1b + browoff[1] + bco);
            LDMX4(qb3[0], b3b + browoff[0] + bco);
            LDMX4(qb3[1], b3b + browoff[1] + bco);
#pragma unroll
            for (int mi = 0; mi < 2; mi++)
#pragma unroll
                for (int ni = 0; ni < 4; ni++) {
                    MMA_F16(ag[mi][ni], am[mi], qb1[ni >> 1][(ni & 1) * 2], qb1[ni >> 1][(ni & 1) * 2 + 1]);
                    MMA_F16(au[mi][ni], am[mi], qb3[ni >> 1][(ni & 1) * 2], qb3[ni >> 1][(ni & 1) * 2 + 1]);
                }
        }
        __syncthreads();
    }

    // epilogue: h = silu(gate)*up -> g_Hh (fp16)
    int g = lane >> 2, tig = lane & 3;
#pragma unroll
    for (int mi = 0; mi < 2; mi++)
#pragma unroll
        for (int half = 0; half < 2; half++) {
            int row = m0 + wm + mi * 16 + g + half * 8;
            if (row < n_e) {
                __half* hr = g_Hh + (size_t)(rbase + row) * FM + f0 + wn;
#pragma unroll
                for (int ni = 0; ni < 4; ni++) {
                    float gv0 = ag[mi][ni][half * 2 + 0];
                    float gv1 = ag[mi][ni][half * 2 + 1];
                    float uv0 = au[mi][ni][half * 2 + 0];
                    float uv1 = au[mi][ni][half * 2 + 1];
                    float h0 = gv0 * uv0 / (1.0f + __expf(-gv0));
                    float h1 = gv1 * uv1 / (1.0f + __expf(-gv1));
                    *reinterpret_cast<__half2*>(hr + ni * 8 + 2 * tig) =
                        __floats2half2_rn(h0, h1);
                }
            }
        }
#undef F1_FILL
}

// ---------------------------------------------------------------------------
// Kernel 6: ffn2, fp16 mma + ldmatrix. BM=128 x BN=64, BK=64 halves, K=FM.
// smem stage: A 16KB | B 8KB = 24KB, double buffered.  (R9 proven config)
// ---------------------------------------------------------------------------
#define F2_STAGE 24576
#define F2_SMEM  (2 * F2_STAGE)

__global__ __launch_bounds__(256) void ffn2_mma(float* __restrict__ out) {
    int e = blockIdx.z;
    int n_e = g_count[e];
    int m0 = blockIdx.x * 128;
    if (m0 >= n_e) return;
    int n0 = blockIdx.y * 64;
    int rbase = g_offset[e];
    extern __shared__ char smem[];
    uint32_t sbase = smem_u32(smem);
    int tid = threadIdx.x, wid = tid >> 5, lane = tid & 31;
    int wm = (wid >> 1) * 32, wn = (wid & 1) * 32;

    int r8 = lane & 7, quad = lane >> 3;
    int aq = quad >> 1;
    int am8 = (quad & 1) * 8;
    int bq = quad & 1;
    int bm8 = (quad >> 1) * 8;
    uint32_t arowoff[2], browoff[2];
#pragma unroll
    for (int mi = 0; mi < 2; mi++)
        arowoff[mi] = (uint32_t)((wm + mi * 16 + am8 + r8) * 128);
#pragma unroll
    for (int np = 0; np < 2; np++)
        browoff[np] = (uint32_t)((wn + np * 16 + bm8 + r8) * 128);

    int lrow = tid >> 3;
    int c16 = tid & 7;
    const __half* asrc[4];
    uint32_t asz[4], adst[4];
#pragma unroll
    for (int i = 0; i < 4; i++) {
        int row = lrow + 32 * i;
        int grow = m0 + row;
        asrc[i] = g_Hh + (size_t)(rbase + ((grow < n_e) ? grow : 0)) * FM + c16 * 8;
        asz[i] = (grow < n_e) ? 16u : 0u;
        adst[i] = (uint32_t)(row * 128 + ((c16 ^ (row & 7)) * 16));
    }
    const __half* bsrc[2];
    uint32_t bdst[2];
#pragma unroll
    for (int i = 0; i < 2; i++) {
        int row = lrow + 32 * i;
        bsrc[i] = g_W2h + ((size_t)e * DM + n0 + row) * FM + c16 * 8;
        bdst[i] = (uint32_t)(row * 128 + ((c16 ^ (row & 7)) * 16));
    }

    float acc[2][4][4];
#pragma unroll
    for (int mi = 0; mi < 2; mi++)
#pragma unroll
        for (int ni = 0; ni < 4; ni++)
#pragma unroll
            for (int j = 0; j < 4; j++) acc[mi][ni][j] = 0.0f;

#define F2_FILL(s, k0) do {                                              \
        uint32_t ab_ = sbase + (s) * F2_STAGE;                           \
        uint32_t bb_ = ab_ + 16384;                                      \
        _Pragma("unroll")                                                \
        for (int i_ = 0; i_ < 4; i_++) CP16Z(ab_ + adst[i_], asrc[i_] + (k0), asz[i_]); \
        _Pragma("unroll")                                                \
        for (int i_ = 0; i_ < 2; i_++) CP16(bb_ + bdst[i_], bsrc[i_] + (k0)); \
    } while (0)

    F2_FILL(0, 0);
    CP_COMMIT();
    const int NKC = FM / 64;
    for (int c = 0; c < NKC; c++) {
        int p = c & 1;
        if (c + 1 < NKC) {
            F2_FILL(p ^ 1, (c + 1) * 64);
            CP_COMMIT();
            CP_WAIT(1);
        } else {
            CP_WAIT(0);
        }
        __syncthreads();
        uint32_t ab = sbase + p * F2_STAGE;
        uint32_t bb = ab + 16384;
#pragma unroll
        for (int s = 0; s < 4; s++) {
            uint32_t aco = (uint32_t)((((2 * s + aq) ^ r8) << 4));
            uint32_t bco = (uint32_t)((((2 * s + bq) ^ r8) << 4));
            uint32_t am[2][4], qb[2][4];
            LDMX4(am[0], ab + arowoff[0] + aco);
            LDMX4(am[1], ab + arowoff[1] + aco);
            LDMX4(qb[0], bb + browoff[0] + bco);
            LDMX4(qb[1], bb + browoff[1] + bco);
#pragma unroll
            for (int mi = 0; mi < 2; mi++)
#pragma unroll
                for (int ni = 0; ni < 4; ni++)
                    MMA_F16(acc[mi][ni], am[mi], qb[ni >> 1][(ni & 1) * 2], qb[ni >> 1][(ni & 1) * 2 + 1]);
        }
        __syncthreads();
    }

    // epilogue: weighted atomicAdd into out[token]
    int g = lane >> 2, tig = lane & 3;
#pragma unroll
    for (int mi = 0; mi < 2; mi++)
#pragma unroll
        for (int half = 0; half < 2; half++) {
            int row = m0 + wm + mi * 16 + g + half * 8;
            if (row < n_e) {
                int gi = rbase + row;
                float wgt = g_rowWeight[gi];
                int tok = g_rowToken[gi];
                float* orow = out + (size_t)tok * DM + n0 + wn;
#pragma unroll
                for (int ni = 0; ni < 4; ni++) {
                    atomicAdd(orow + ni * 8 + 2 * tig,     wgt * acc[mi][ni][half * 2 + 0]);
                    atomicAdd(orow + ni * 8 + 2 * tig + 1, wgt * acc[mi][ni][half * 2 + 1]);
                }
            }
        }
#undef F2_FILL
}

// ---------------------------------------------------------------------------
// Launch
// ---------------------------------------------------------------------------
extern "C" void kernel_launch(void* const* d_in, const int* in_sizes, int n_in,
                              void* d_out, int out_size) {
    const float* x  = (const float*)d_in[0];   // [B,T,D]
    const float* Wr = (const float*)d_in[1];   // [D,E]
    const float* W1 = (const float*)d_in[2];   // [E,D,F]
    const float* W3 = (const float*)d_in[3];   // [E,D,F]
    const float* W2 = (const float*)d_in[4];   // [E,F,D]
    float* out = (float*)d_out;

    cudaFuncSetAttribute(ffn1_mma, cudaFuncAttributeMaxDynamicSharedMemorySize, F1_SMEM);
    cudaFuncSetAttribute(ffn2_mma, cudaFuncAttributeMaxDynamicSharedMemorySize, F2_SMEM);

    zero_kernel<<<4096, 256>>>(out);
    router_kernel<<<NT, 256>>>(x, Wr);          // also writes g_Xh
    prefix_scatter_kernel<<<1, 256>>>(out, out_size);

    transpose_all<<<T_TOTAL, 256>>>(W1, W3, W2);

    ffn1_mma<<<dim3(32, FM / 64, EM), 256, F1_SMEM>>>();
    ffn2_mma<<<dim3(32, DM / 64, EM), 256, F2_SMEM>>>(out);
}